// round 15
// baseline (speedup 1.0000x reference)
#include <cuda_runtime.h>
#include <cuda_bf16.h>
#include <cstdint>

#define N_NODES 100000
#define N_PAD (N_NODES + 256)
#define N_EDGESC 1600000
#define N_GRAPHS 512
#define DH 128
#define DLAT 64
#define NCOND 7
#define BN_EPS 1e-5f
#define NSM 148

// ================= scratch (device globals; zero-initialized at load) =================
__device__ uint4 g_a[N_PAD * 32];        // gather out (interleaved hi/lo)
__device__ uint4 g_h[N_PAD * 32];        // GEMM1 out
__device__ uint4 g_x[N_PAD * 32];        // GEMM2 out (layer output)
__device__ uint4 g_Bpk1[3 * 128 * 32];   // W1 fragment packs
__device__ int g_cnt[N_NODES];
__device__ int g_rowptr[N_NODES + 1];
__device__ int g_bsum[128];
__device__ int g_csr[N_EDGESC];
__device__ float g_sum[3 * DH];
__device__ float g_sumsq[3 * DH];
__device__ float g_pooled[N_GRAPHS * DH];
__device__ float g_pa[DH];
__device__ float g_pc[DH];
__device__ float g_h1[N_GRAPHS * DLAT];
__device__ float g_fa[DLAT];
__device__ float g_fc[DLAT];

// ================= helpers =================
__device__ __forceinline__ float leaky(float x) { return fmaxf(x, 0.2f * x); }
__device__ __forceinline__ void red_add_v2(float* p, float a, float b) {
    asm volatile("red.global.add.v2.f32 [%0], {%1,%2};"
                 :: "l"(p), "f"(a), "f"(b) : "memory");
}
__device__ __forceinline__ uint32_t bf2bits(__nv_bfloat162 v) {
    return *reinterpret_cast<uint32_t*>(&v);
}
__device__ __forceinline__ __nv_bfloat162 bits2bf2(uint32_t v) {
    return *reinterpret_cast<__nv_bfloat162*>(&v);
}
__device__ __forceinline__ float4 dec4(uint4 v) {
    float2 h0 = __bfloat1622float2(bits2bf2(v.x));
    float2 l0 = __bfloat1622float2(bits2bf2(v.y));
    float2 h1 = __bfloat1622float2(bits2bf2(v.z));
    float2 l1 = __bfloat1622float2(bits2bf2(v.w));
    return make_float4(h0.x + l0.x, h0.y + l0.y, h1.x + l1.x, h1.y + l1.y);
}
__device__ __forceinline__ uint4 enc4(float4 a) {
    __nv_bfloat162 H0 = __floats2bfloat162_rn(a.x, a.y);
    __nv_bfloat162 H1 = __floats2bfloat162_rn(a.z, a.w);
    float2 f0 = __bfloat1622float2(H0), f1 = __bfloat1622float2(H1);
    __nv_bfloat162 L0 = __floats2bfloat162_rn(a.x - f0.x, a.y - f0.y);
    __nv_bfloat162 L1 = __floats2bfloat162_rn(a.z - f1.x, a.w - f1.y);
    return make_uint4(bf2bits(H0), bf2bits(L0), bf2bits(H1), bf2bits(L1));
}
__device__ __forceinline__ void mma_bf16(float* d, uint32_t a0, uint32_t a1,
                                         uint32_t a2, uint32_t a3,
                                         uint32_t b0, uint32_t b1) {
    asm volatile(
        "mma.sync.aligned.m16n8k16.row.col.f32.bf16.bf16.f32 "
        "{%0,%1,%2,%3}, {%4,%5,%6,%7}, {%8,%9}, {%0,%1,%2,%3};"
        : "+f"(d[0]), "+f"(d[1]), "+f"(d[2]), "+f"(d[3])
        : "r"(a0), "r"(a1), "r"(a2), "r"(a3), "r"(b0), "r"(b1));
}
// fragment-pack one (k, n) weight value into bf16 hi/lo at smem/global pack buffer
__device__ __forceinline__ void pack_w(__nv_bfloat16* base, int k, int n, float ws) {
    __nv_bfloat16 hi = __float2bfloat16(ws);
    __nv_bfloat16 lo = __float2bfloat16(ws - __bfloat162float(hi));
    int ks = k >> 4, kr = k & 15;
    int slot = kr >> 3;
    int qid = (kr & 7) >> 1;
    int half = kr & 1;
    int t = n >> 3, gid = n & 7;
    int lane = gid * 4 + qid;
    __nv_bfloat16* p = base + ((size_t)(ks * 16 + t) * 32 + lane) * 8;
    p[slot * 2 + half] = hi;
    p[4 + slot * 2 + half] = lo;
}

// ================= zero (stats + pooled + cnt in one launch) =================
__global__ void zero3(float4* sum4, float4* sq4, float4* pool4, float4* cnt4,
                      int pool4n, int cnt4n) {
    int i = blockIdx.x * blockDim.x + threadIdx.x;
    if (i < pool4n) pool4[i] = make_float4(0.f, 0.f, 0.f, 0.f);
    if (i < cnt4n) cnt4[i] = make_float4(0.f, 0.f, 0.f, 0.f);
    if (i < 3 * DH / 4) {
        sum4[i] = make_float4(0.f, 0.f, 0.f, 0.f);
        sq4[i] = make_float4(0.f, 0.f, 0.f, 0.f);
    }
}

// ================= CSR build =================
__global__ void hist_k(const int* __restrict__ dst, int* __restrict__ cnt, int nE) {
    int i = blockIdx.x * blockDim.x + threadIdx.x;
    if (i < nE) atomicAdd(&cnt[dst[i]], 1);
}
__global__ void scan_block(const int* __restrict__ cnt, int* __restrict__ excl,
                           int* __restrict__ bsum, int n) {
    __shared__ int sm[1024];
    int i = blockIdx.x * 1024 + threadIdx.x;
    int v = (i < n) ? cnt[i] : 0;
    sm[threadIdx.x] = v;
    __syncthreads();
    for (int off = 1; off < 1024; off <<= 1) {
        int t = (threadIdx.x >= off) ? sm[threadIdx.x - off] : 0;
        __syncthreads();
        sm[threadIdx.x] += t;
        __syncthreads();
    }
    if (i < n) excl[i] = sm[threadIdx.x] - v;
    if (threadIdx.x == 1023) bsum[blockIdx.x] = sm[1023];
}
__global__ void __launch_bounds__(256) add_off2(
    int* __restrict__ rowptr, const int* __restrict__ bsum,
    int* __restrict__ cursor, int n, int nE, int nb) {
    __shared__ int soff;
    int t = threadIdx.x;
    int v = (t < nb && t < blockIdx.x) ? bsum[t] : 0;
#pragma unroll
    for (int off = 16; off > 0; off >>= 1) v += __shfl_xor_sync(0xffffffff, v, off);
    __shared__ int warpsum[8];
    if ((t & 31) == 0) warpsum[t >> 5] = v;
    __syncthreads();
    if (t == 0) {
        int s = 0;
#pragma unroll
        for (int w = 0; w < 8; w++) s += warpsum[w];
        soff = s;
    }
    __syncthreads();
    int base = blockIdx.x * 1024;
#pragma unroll
    for (int it = 0; it < 4; it++) {
        int i = base + it * 256 + t;
        if (i < n) {
            int val = rowptr[i] + soff;
            rowptr[i] = val;
            cursor[i] = val;
        }
    }
    if (blockIdx.x == 0 && t == 0) rowptr[n] = nE;
}
__global__ void scatter_k(const int* __restrict__ src, const int* __restrict__ dst,
                          int* __restrict__ cursor, int* __restrict__ csr, int nE) {
    int i = blockIdx.x * blockDim.x + threadIdx.x;
    if (i < nE) {
        int pos = atomicAdd(&cursor[dst[i]], 1);
        csr[pos] = src[i];
    }
}

// ================= gather: h = x[node] + sum_nb x[nb]; interleaved in/out =================
__global__ void __launch_bounds__(256) gather_i(
    const float4* __restrict__ xf, const uint4* __restrict__ xc,
    const int* __restrict__ rowptr, const int* __restrict__ csr,
    uint4* __restrict__ out, int M, int splitIn) {
    int node = blockIdx.x * 8 + (threadIdx.x >> 5);
    if (node >= M) return;
    int lane = threadIdx.x & 31;
    int e0 = __ldg(rowptr + node), e1 = __ldg(rowptr + node + 1);
    float4 acc;
    if (!splitIn) {
        acc = __ldg(xf + (size_t)node * 32 + lane);
        int e = e0;
        for (; e + 16 <= e1; e += 16) {
            int s[16];
#pragma unroll
            for (int u = 0; u < 16; u++) s[u] = __ldg(csr + e + u);
            float4 v[16];
#pragma unroll
            for (int u = 0; u < 16; u++) v[u] = __ldg(xf + (size_t)s[u] * 32 + lane);
#pragma unroll
            for (int u = 0; u < 16; u++) {
                acc.x += v[u].x; acc.y += v[u].y; acc.z += v[u].z; acc.w += v[u].w;
            }
        }
        for (; e + 4 <= e1; e += 4) {
            int s[4];
#pragma unroll
            for (int u = 0; u < 4; u++) s[u] = __ldg(csr + e + u);
            float4 v[4];
#pragma unroll
            for (int u = 0; u < 4; u++) v[u] = __ldg(xf + (size_t)s[u] * 32 + lane);
#pragma unroll
            for (int u = 0; u < 4; u++) {
                acc.x += v[u].x; acc.y += v[u].y; acc.z += v[u].z; acc.w += v[u].w;
            }
        }
        for (; e < e1; e++) {
            int s = __ldg(csr + e);
            float4 v = __ldg(xf + (size_t)s * 32 + lane);
            acc.x += v.x; acc.y += v.y; acc.z += v.z; acc.w += v.w;
        }
    } else {
        acc = dec4(__ldg(xc + (size_t)node * 32 + lane));
        int e = e0;
        for (; e + 16 <= e1; e += 16) {
            int s[16];
#pragma unroll
            for (int u = 0; u < 16; u++) s[u] = __ldg(csr + e + u);
            uint4 w[16];
#pragma unroll
            for (int u = 0; u < 16; u++) w[u] = __ldg(xc + (size_t)s[u] * 32 + lane);
#pragma unroll
            for (int u = 0; u < 16; u++) {
                float4 v = dec4(w[u]);
                acc.x += v.x; acc.y += v.y; acc.z += v.z; acc.w += v.w;
            }
        }
        for (; e + 4 <= e1; e += 4) {
            int s[4];
#pragma unroll
            for (int u = 0; u < 4; u++) s[u] = __ldg(csr + e + u);
            uint4 w[4];
#pragma unroll
            for (int u = 0; u < 4; u++) w[u] = __ldg(xc + (size_t)s[u] * 32 + lane);
#pragma unroll
            for (int u = 0; u < 4; u++) {
                float4 v = dec4(w[u]);
                acc.x += v.x; acc.y += v.y; acc.z += v.z; acc.w += v.w;
            }
        }
        for (; e < e1; e++) {
            int s = __ldg(csr + e);
            float4 v = dec4(__ldg(xc + (size_t)s * 32 + lane));
            acc.x += v.x; acc.y += v.y; acc.z += v.z; acc.w += v.w;
        }
    }
    out[(size_t)node * 32 + lane] = enc4(acc);
}

// ================= W1 prep: all 3 layers in one launch =================
__global__ void __launch_bounds__(128) wprep1all(
    const float* __restrict__ W, uint4* __restrict__ Bpk) {
    int l = blockIdx.x >> 7;
    int n = blockIdx.x & 127, k = threadIdx.x;
    float w = W[(size_t)l * DH * DH + k * DH + n];
    pack_w(reinterpret_cast<__nv_bfloat16*>(Bpk + (size_t)l * 4096), k, n, w);
}

// ================= smem layout (256-row tiles, persistent, warp-autonomous) =================
#define ASW 68
#define A_ROWS 256
#define SM_AL_OFF (A_ROWS * ASW * 4)       // 69632
#define SM_B_OFF (2 * A_ROWS * ASW * 4)    // 139264
#define SM_BIAS_OFF (SM_B_OFF + 65536)     // 204800
#define SM_STAT_OFF (SM_BIAS_OFF + 512)    // 205312
#define GEMM_SMEM (SM_STAT_OFF + 8192)     // 213504

__device__ __forceinline__ void stage_warp_A(const uint4* __restrict__ A,
                                             uint32_t* Ash, uint32_t* Asl,
                                             int warp, int lane, int row0) {
    int m0 = warp * 32;
#pragma unroll
    for (int i = 0; i < 32; i++) {
        int r = m0 + i;
        uint4 v = __ldg(A + (size_t)(row0 + r) * 32 + lane);
        *(uint2*)(Ash + r * ASW + 2 * lane) = make_uint2(v.x, v.z);
        *(uint2*)(Asl + r * ASW + 2 * lane) = make_uint2(v.y, v.w);
    }
}

__device__ __forceinline__ void mainloop(
    const uint32_t* Ash, const uint32_t* Asl, const uint4* Bs,
    int warp, int lane, float acc[2][16][4]) {
    int m0 = warp * 32;
    int gid = lane >> 2, qid = lane & 3;
#pragma unroll
    for (int mt = 0; mt < 2; mt++)
#pragma unroll
        for (int t = 0; t < 16; t++)
#pragma unroll
            for (int j = 0; j < 4; j++) acc[mt][t][j] = 0.f;

    const uint32_t *rh0[2], *rh1[2], *rl0[2], *rl1[2];
#pragma unroll
    for (int mt = 0; mt < 2; mt++) {
        rh0[mt] = Ash + (m0 + 16 * mt + gid) * ASW;
        rh1[mt] = Ash + (m0 + 16 * mt + gid + 8) * ASW;
        rl0[mt] = Asl + (m0 + 16 * mt + gid) * ASW;
        rl1[mt] = Asl + (m0 + 16 * mt + gid + 8) * ASW;
    }
#pragma unroll
    for (int ks = 0; ks < 8; ks++) {
        int kb = ks * 8 + qid;
        uint32_t Ahf[2][4], Alf[2][4];
#pragma unroll
        for (int mt = 0; mt < 2; mt++) {
            Ahf[mt][0] = rh0[mt][kb]; Ahf[mt][1] = rh1[mt][kb];
            Ahf[mt][2] = rh0[mt][kb + 4]; Ahf[mt][3] = rh1[mt][kb + 4];
            Alf[mt][0] = rl0[mt][kb]; Alf[mt][1] = rl1[mt][kb];
            Alf[mt][2] = rl0[mt][kb + 4]; Alf[mt][3] = rl1[mt][kb + 4];
        }
        const uint4* bp = Bs + ks * 512 + lane;
#pragma unroll
        for (int t = 0; t < 16; t++) {
            uint4 bv = bp[t * 32];
#pragma unroll
            for (int mt = 0; mt < 2; mt++) {
                mma_bf16(acc[mt][t], Ahf[mt][0], Ahf[mt][1], Ahf[mt][2], Ahf[mt][3], bv.x, bv.y);
                mma_bf16(acc[mt][t], Ahf[mt][0], Ahf[mt][1], Ahf[mt][2], Ahf[mt][3], bv.z, bv.w);
                mma_bf16(acc[mt][t], Alf[mt][0], Alf[mt][1], Alf[mt][2], Alf[mt][3], bv.x, bv.y);
            }
        }
    }
}

__device__ __forceinline__ void store_pair(uint32_t* orow, int j, float v0, float v1) {
    __nv_bfloat162 H = __floats2bfloat162_rn(v0, v1);
    float2 f = __bfloat1622float2(H);
    __nv_bfloat162 L = __floats2bfloat162_rn(v0 - f.x, v1 - f.y);
    *(uint2*)(orow + 2 * j) = make_uint2(bf2bits(H), bf2bits(L));
}

// ================= GEMM1 persistent warp-autonomous: + leaky + out + fused stats =================
__global__ void __launch_bounds__(256, 1) gemm1_stats(
    const uint4* __restrict__ A, const uint4* __restrict__ Bpk,
    const float* __restrict__ bias, uint32_t* __restrict__ out,
    float* __restrict__ gsum, float* __restrict__ gsq, int M, int nTiles) {
    extern __shared__ char smem[];
    uint32_t* Ash = (uint32_t*)smem;
    uint32_t* Asl = (uint32_t*)(smem + SM_AL_OFF);
    uint4* Bs = (uint4*)(smem + SM_B_OFF);
    float* sb = (float*)(smem + SM_BIAS_OFF);
    float* wstat = (float*)(smem + SM_STAT_OFF);
    int tid = threadIdx.x;
    int warp = tid >> 5, lane = tid & 31;
    int gid = lane >> 2, qid = lane & 3;

    if (tid < 128) sb[tid] = bias[tid];
    float* mystat = wstat + warp * 256;
#pragma unroll
    for (int i = lane; i < 256; i += 32) mystat[i] = 0.f;
#pragma unroll
    for (int it = 0; it < 16; it++) Bs[it * 256 + tid] = __ldg(Bpk + it * 256 + tid);
    __syncthreads();

    for (int tile = blockIdx.x; tile < nTiles; tile += NSM) {
        int row0 = tile << 8;
        __syncwarp();
        stage_warp_A(A, Ash, Asl, warp, lane, row0);
        __syncwarp();
        float acc[2][16][4];
        mainloop(Ash, Asl, Bs, warp, lane, acc);

        float cs[32], cq[32];
#pragma unroll
        for (int i = 0; i < 32; i++) { cs[i] = 0.f; cq[i] = 0.f; }
#pragma unroll
        for (int mt = 0; mt < 2; mt++) {
            int r0 = row0 + warp * 32 + 16 * mt + gid;
            int r1 = r0 + 8;
            uint32_t* orow0 = out + (size_t)r0 * 128;
            uint32_t* orow1 = out + (size_t)r1 * 128;
            bool in0 = (r0 < M), in1 = (r1 < M);
#pragma unroll
            for (int t = 0; t < 16; t++) {
                int c = t * 8 + qid * 2;
                int j = t * 4 + qid;
                float b0 = sb[c], b1 = sb[c + 1];
                float v00 = leaky(acc[mt][t][0] + b0);
                float v01 = leaky(acc[mt][t][1] + b1);
                float v10 = leaky(acc[mt][t][2] + b0);
                float v11 = leaky(acc[mt][t][3] + b1);
                store_pair(orow0, j, v00, v01);
                store_pair(orow1, j, v10, v11);
                if (!in0) { v00 = 0.f; v01 = 0.f; }
                if (!in1) { v10 = 0.f; v11 = 0.f; }
                cs[2 * t] += v00 + v10;
                cs[2 * t + 1] += v01 + v11;
                cq[2 * t] += v00 * v00 + v10 * v10;
                cq[2 * t + 1] += v01 * v01 + v11 * v11;
            }
        }
#pragma unroll
        for (int i = 0; i < 32; i++) {
#pragma unroll
            for (int off = 4; off < 32; off <<= 1) {
                cs[i] += __shfl_xor_sync(0xffffffff, cs[i], off);
                cq[i] += __shfl_xor_sync(0xffffffff, cq[i], off);
            }
        }
        if (lane < 4) {
#pragma unroll
            for (int t = 0; t < 16; t++) {
                int c = t * 8 + lane * 2;
                mystat[c] += cs[2 * t];
                mystat[c + 1] += cs[2 * t + 1];
                mystat[128 + c] += cq[2 * t];
                mystat[128 + c + 1] += cq[2 * t + 1];
            }
        }
    }
    __syncthreads();
    if (tid < 128) {
        float s = 0.f;
#pragma unroll
        for (int w = 0; w < 8; w++) s += wstat[w * 256 + tid];
        atomicAdd(&gsum[tid], s);
    } else {
        int c = tid - 128;
        float q = 0.f;
#pragma unroll
        for (int w = 0; w < 8; w++) q += wstat[w * 256 + 128 + c];
        atomicAdd(&gsq[c], q);
    }
}

// ================= GEMM2 persistent: in-CTA BN-fold + W2 pack; mode0: store; mode1: pool =================
__global__ void __launch_bounds__(256, 1) gemm2_pool(
    const uint4* __restrict__ A,
    const float* __restrict__ W, const float* __restrict__ bvec,
    const float* __restrict__ sum, const float* __restrict__ sumsq,
    const float* __restrict__ gam, const float* __restrict__ bet, float Mf,
    uint32_t* __restrict__ out,
    const int* __restrict__ batch, float* __restrict__ pooled,
    int M, int nTiles, int doPool) {
    extern __shared__ char smem[];
    uint32_t* Ash = (uint32_t*)smem;
    uint32_t* Asl = (uint32_t*)(smem + SM_AL_OFF);
    uint4* Bs = (uint4*)(smem + SM_B_OFF);
    float* sb = (float*)(smem + SM_BIAS_OFF);
    float* sa = (float*)(smem + SM_STAT_OFF);            // a[k]
    float* sc = (float*)(smem + SM_STAT_OFF + 512);      // c[k]
    float* sred = (float*)(smem + SM_STAT_OFF + 1024);   // bias partials [2][128]
    int tid = threadIdx.x;
    int warp = tid >> 5, lane = tid & 31;
    int gid = lane >> 2, qid = lane & 3;

    // ---- prologue: BN affine from raw sums, pack W2 into Bs, fold bias ----
    if (tid < 128) {
        float m = sum[tid] / Mf;
        float v = sumsq[tid] / Mf - m * m;
        float r = rsqrtf(v + BN_EPS);
        sa[tid] = gam[tid] * r;
        sc[tid] = bet[tid] - gam[tid] * m * r;
    }
    __syncthreads();
    {
        int n = tid & 127, kh = tid >> 7;
        __nv_bfloat16* bsp = (__nv_bfloat16*)Bs;
        float bpart = 0.f;
#pragma unroll 4
        for (int kk = 0; kk < 64; kk++) {
            int k = kh * 64 + kk;
            float w = __ldg(W + (size_t)k * DH + n);
            bpart += sc[k] * w;
            pack_w(bsp, k, n, sa[k] * w);
        }
        sred[kh * 128 + n] = bpart;
    }
    __syncthreads();
    if (tid < 128) sb[tid] = bvec[tid] + sred[tid] + sred[128 + tid];
    __syncthreads();

    for (int tile = blockIdx.x; tile < nTiles; tile += NSM) {
        int row0 = tile << 8;
        __syncwarp();
        stage_warp_A(A, Ash, Asl, warp, lane, row0);
        __syncwarp();
        float acc[2][16][4];
        mainloop(Ash, Asl, Bs, warp, lane, acc);

        if (!doPool) {
#pragma unroll
            for (int mt = 0; mt < 2; mt++) {
                int r0 = row0 + warp * 32 + 16 * mt + gid;
                int r1 = r0 + 8;
                uint32_t* orow0 = out + (size_t)r0 * 128;
                uint32_t* orow1 = out + (size_t)r1 * 128;
#pragma unroll
                for (int t = 0; t < 16; t++) {
                    int c = t * 8 + qid * 2;
                    int j = t * 4 + qid;
                    float b0 = sb[c], b1 = sb[c + 1];
                    store_pair(orow0, j, leaky(acc[mt][t][0] + b0), leaky(acc[mt][t][1] + b1));
                    store_pair(orow1, j, leaky(acc[mt][t][2] + b0), leaky(acc[mt][t][3] + b1));
                }
            }
        } else {
#pragma unroll
            for (int mt = 0; mt < 2; mt++) {
                int r0 = row0 + warp * 32 + 16 * mt + gid;
                int r1 = r0 + 8;
                int b0g = (r0 < M) ? __ldg(batch + r0) : 0;
                int b1g = (r1 < M) ? __ldg(batch + r1) : 0;
#pragma unroll
                for (int t = 0; t < 16; t++) {
                    int c = t * 8 + qid * 2;
                    float b0 = sb[c], b1 = sb[c + 1];
                    if (r0 < M)
                        red_add_v2(pooled + (size_t)b0g * DH + c,
                                   leaky(acc[mt][t][0] + b0), leaky(acc[mt][t][1] + b1));
                    if (r1 < M)
                        red_add_v2(pooled + (size_t)b1g * DH + c,
                                   leaky(acc[mt][t][2] + b0), leaky(acc[mt][t][3] + b1));
                }
            }
        }
    }
}

// ================= small column stats (pooled / h1) =================
__global__ void colstats(const float* __restrict__ data, int rows, int cols,
                         const float* __restrict__ g, const float* __restrict__ b,
                         float* __restrict__ oa, float* __restrict__ oc) {
    int col = blockIdx.x;
    int t = threadIdx.x;
    float s = 0.f, q = 0.f;
    for (int r = t; r < rows; r += blockDim.x) {
        float v = data[(size_t)r * cols + col];
        s += v; q += v * v;
    }
    __shared__ float ss[256], qq[256];
    ss[t] = s; qq[t] = q;
    __syncthreads();
    for (int off = 128; off > 0; off >>= 1) {
        if (t < off) { ss[t] += ss[t + off]; qq[t] += qq[t + off]; }
        __syncthreads();
    }
    if (t == 0) {
        float m = ss[0] / rows;
        float v = qq[0] / rows - m * m;
        float r = rsqrtf(v + BN_EPS);
        oa[col] = g[col] * r;
        oc[col] = b[col] - g[col] * m * r;
    }
}

// ================= head =================
__global__ void __launch_bounds__(64) head1(
    const float* __restrict__ pooled, const float* __restrict__ pa, const float* __restrict__ pc,
    const float* __restrict__ fcW, const float* __restrict__ fcb,
    const float* __restrict__ feats,
    const float* __restrict__ cW1, const float* __restrict__ cb1,
    const float* __restrict__ cW2, const float* __restrict__ cb2,
    const float* __restrict__ fW1, const float* __restrict__ fb1,
    float* __restrict__ h1out) {
    int g = blockIdx.x;
    int j = threadIdx.x;
    __shared__ float cat[DLAT + 8];
    float o = fcb[j];
    const float* pr = pooled + (size_t)g * DH;
    for (int k = 0; k < DH; k++) o += (pr[k] * pa[k] + pc[k]) * fcW[k * DLAT + j];
    cat[j] = o;
    if (j < 8) {
        float c1[8];
#pragma unroll
        for (int i = 0; i < 8; i++) {
            float a = cb1[i];
#pragma unroll
            for (int m = 0; m < NCOND; m++) a += feats[g * NCOND + m] * cW1[m * 8 + i];
            c1[i] = fmaxf(a, 0.f);
        }
        float o2 = cb2[j];
#pragma unroll
        for (int i = 0; i < 8; i++) o2 += c1[i] * cW2[i * 8 + j];
        cat[DLAT + j] = o2;
    }
    __syncthreads();
    float h = fb1[j];
    for (int k = 0; k < DLAT + 8; k++) h += cat[k] * fW1[k * DLAT + j];
    h1out[(size_t)g * DLAT + j] = leaky(h);
}

__global__ void __launch_bounds__(64) head2(
    const float* __restrict__ h1, const float* __restrict__ fa, const float* __restrict__ fc,
    const float* __restrict__ fW2, const float* __restrict__ fb2,
    float* __restrict__ out) {
    int g = blockIdx.x;
    int j = threadIdx.x;
    __shared__ float hn[DLAT];
    hn[j] = h1[(size_t)g * DLAT + j] * fa[j] + fc[j];
    __syncthreads();
    float o = fb2[j];
    for (int k = 0; k < DLAT; k++) o += hn[k] * fW2[k * DLAT + j];
    out[(size_t)g * DLAT + j] = o;
}

// ================= launch =================
extern "C" void kernel_launch(void* const* d_in, const int* in_sizes, int n_in,
                              void* d_out, int out_size) {
    const float* x      = (const float*)d_in[0];
    const int*   ei     = (const int*)d_in[1];
    const int*   batch  = (const int*)d_in[2];
    const float* feats  = (const float*)d_in[3];
    const float* convW1 = (const float*)d_in[4];
    const float* convb1 = (const float*)d_in[5];
    const float* convg1 = (const float*)d_in[6];
    const float* convbb1= (const float*)d_in[7];
    const float* convW2 = (const float*)d_in[8];
    const float* convb2 = (const float*)d_in[9];
    const float* bng    = (const float*)d_in[10];
    const float* bnb    = (const float*)d_in[11];
    const float* fcW    = (const float*)d_in[12];
    const float* fcb    = (const float*)d_in[13];
    const float* cW1    = (const float*)d_in[14];
    const float* cb1    = (const float*)d_in[15];
    const float* cW2    = (const float*)d_in[16];
    const float* cb2    = (const float*)d_in[17];
    const float* fW1    = (const float*)d_in[18];
    const float* fb1    = (const float*)d_in[19];
    const float* fg     = (const float*)d_in[20];
    const float* fb_    = (const float*)d_in[21];
    const float* fW2    = (const float*)d_in[22];
    const float* fb2    = (const float*)d_in[23];
    float* dout = (float*)d_out;

    int nE = in_sizes[1] / 2;
    const int* src = ei;
    const int* dst = ei + nE;
    int M = in_sizes[0] / DH;
    int G = in_sizes[3] / NCOND;

    uint4 *p_a, *p_h, *p_x, *p_Bpk1;
    float *p_sum, *p_sq, *p_pool, *p_pa, *p_pc, *p_h1, *p_fa, *p_fc;
    int *p_cnt, *p_rowptr, *p_bsum, *p_csr;
    cudaGetSymbolAddress((void**)&p_a, g_a);
    cudaGetSymbolAddress((void**)&p_h, g_h);
    cudaGetSymbolAddress((void**)&p_x, g_x);
    cudaGetSymbolAddress((void**)&p_Bpk1, g_Bpk1);
    cudaGetSymbolAddress((void**)&p_cnt, g_cnt);
    cudaGetSymbolAddress((void**)&p_rowptr, g_rowptr);
    cudaGetSymbolAddress((void**)&p_bsum, g_bsum);
    cudaGetSymbolAddress((void**)&p_csr, g_csr);
    cudaGetSymbolAddress((void**)&p_sum, g_sum);
    cudaGetSymbolAddress((void**)&p_sq, g_sumsq);
    cudaGetSymbolAddress((void**)&p_pool, g_pooled);
    cudaGetSymbolAddress((void**)&p_pa, g_pa);
    cudaGetSymbolAddress((void**)&p_pc, g_pc);
    cudaGetSymbolAddress((void**)&p_h1, g_h1);
    cudaGetSymbolAddress((void**)&p_fa, g_fa);
    cudaGetSymbolAddress((void**)&p_fc, g_fc);

    cudaFuncSetAttribute(gemm1_stats, cudaFuncAttributeMaxDynamicSharedMemorySize, GEMM_SMEM);
    cudaFuncSetAttribute(gemm2_pool, cudaFuncAttributeMaxDynamicSharedMemorySize, GEMM_SMEM);

    // ---- zero stats + pooled + cnt in one launch ----
    int cnt4n = N_NODES / 4;
    int zgrid = (cnt4n > N_GRAPHS * DH / 4 ? cnt4n : N_GRAPHS * DH / 4);
    zero3<<<(zgrid + 255) / 256, 256>>>(
        (float4*)p_sum, (float4*)p_sq, (float4*)p_pool, (float4*)p_cnt,
        N_GRAPHS * DH / 4, cnt4n);

    // ---- CSR build ----
    hist_k<<<(nE + 255) / 256, 256>>>(dst, p_cnt, nE);
    int nb = (M + 1023) / 1024;
    scan_block<<<nb, 1024>>>(p_cnt, p_rowptr, p_bsum, M);
    add_off2<<<nb, 256>>>(p_rowptr, p_bsum, p_cnt, M, nE, nb);
    scatter_k<<<(nE + 255) / 256, 256>>>(src, dst, p_cnt, p_csr, nE);

    // ---- pack all W1 in one launch ----
    wprep1all<<<3 * DH, DH>>>(convW1, p_Bpk1);

    int nTiles = (M + 255) / 256;
    for (int l = 0; l < 3; l++) {
        gather_i<<<(M + 7) / 8, 256>>>(
            (const float4*)x, (const uint4*)p_x, p_rowptr, p_csr, p_a, M, (l == 0) ? 0 : 1);
        gemm1_stats<<<NSM, 256, GEMM_SMEM>>>(
            p_a, p_Bpk1 + (size_t)l * 4096, convb1 + l * DH, (uint32_t*)p_h,
            p_sum + l * DH, p_sq + l * DH, M, nTiles);
        gemm2_pool<<<NSM, 256, GEMM_SMEM>>>(
            p_h, convW2 + (size_t)l * DH * DH, convb2 + l * DH,
            p_sum + l * DH, p_sq + l * DH, convg1 + l * DH, convbb1 + l * DH, (float)M,
            (uint32_t*)p_x, batch, p_pool, M, nTiles, (l == 2) ? 1 : 0);
    }

    colstats<<<DH, 256>>>(p_pool, G, DH, bng, bnb, p_pa, p_pc);
    head1<<<G, 64>>>(p_pool, p_pa, p_pc, fcW, fcb, feats, cW1, cb1, cW2, cb2, fW1, fb1, p_h1);
    colstats<<<DLAT, 256>>>(p_h1, G, DLAT, fg, fb_, p_fa, p_fc);
    head2<<<G, 64>>>(p_h1, p_fa, p_fc, fW2, fb2, dout);
}

// round 16
// speedup vs baseline: 1.0458x; 1.0458x over previous
#include <cuda_runtime.h>
#include <cuda_bf16.h>
#include <cstdint>

#define N_NODES 100000
#define N_PAD (N_NODES + 256)
#define N_EDGESC 1600000
#define N_GRAPHS 512
#define DH 128
#define DLAT 64
#define NCOND 7
#define BN_EPS 1e-5f
#define NSM 148

// ================= scratch (device globals; zero-initialized at load) =================
__device__ uint4 g_a[N_PAD * 32];        // gather out (interleaved hi/lo)
__device__ uint4 g_h[N_PAD * 32];        // GEMM1 out
__device__ uint4 g_x[N_PAD * 32];        // GEMM2 out (layer output)
__device__ uint4 g_Bpk1[3 * 128 * 32];   // W1 fragment packs
__device__ uint4 g_Bpk2[128 * 32];       // W2 fragment pack (per layer)
__device__ float g_bias[DH];
__device__ int g_cnt[N_NODES];
__device__ int g_rowptr[N_NODES + 1];
__device__ int g_bsum[128];
__device__ int g_csr[N_EDGESC];
__device__ float g_sum[3 * DH];
__device__ float g_sumsq[3 * DH];
__device__ float g_pooled[N_GRAPHS * DH];
__device__ float g_pa[DH];
__device__ float g_pc[DH];
__device__ float g_h1[N_GRAPHS * DLAT];
__device__ float g_fa[DLAT];
__device__ float g_fc[DLAT];

// ================= helpers =================
__device__ __forceinline__ float leaky(float x) { return fmaxf(x, 0.2f * x); }
__device__ __forceinline__ void red_add_v2(float* p, float a, float b) {
    asm volatile("red.global.add.v2.f32 [%0], {%1,%2};"
                 :: "l"(p), "f"(a), "f"(b) : "memory");
}
__device__ __forceinline__ uint32_t bf2bits(__nv_bfloat162 v) {
    return *reinterpret_cast<uint32_t*>(&v);
}
__device__ __forceinline__ __nv_bfloat162 bits2bf2(uint32_t v) {
    return *reinterpret_cast<__nv_bfloat162*>(&v);
}
__device__ __forceinline__ float4 dec4(uint4 v) {
    float2 h0 = __bfloat1622float2(bits2bf2(v.x));
    float2 l0 = __bfloat1622float2(bits2bf2(v.y));
    float2 h1 = __bfloat1622float2(bits2bf2(v.z));
    float2 l1 = __bfloat1622float2(bits2bf2(v.w));
    return make_float4(h0.x + l0.x, h0.y + l0.y, h1.x + l1.x, h1.y + l1.y);
}
__device__ __forceinline__ uint4 enc4(float4 a) {
    __nv_bfloat162 H0 = __floats2bfloat162_rn(a.x, a.y);
    __nv_bfloat162 H1 = __floats2bfloat162_rn(a.z, a.w);
    float2 f0 = __bfloat1622float2(H0), f1 = __bfloat1622float2(H1);
    __nv_bfloat162 L0 = __floats2bfloat162_rn(a.x - f0.x, a.y - f0.y);
    __nv_bfloat162 L1 = __floats2bfloat162_rn(a.z - f1.x, a.w - f1.y);
    return make_uint4(bf2bits(H0), bf2bits(L0), bf2bits(H1), bf2bits(L1));
}
__device__ __forceinline__ void mma_bf16(float* d, uint32_t a0, uint32_t a1,
                                         uint32_t a2, uint32_t a3,
                                         uint32_t b0, uint32_t b1) {
    asm volatile(
        "mma.sync.aligned.m16n8k16.row.col.f32.bf16.bf16.f32 "
        "{%0,%1,%2,%3}, {%4,%5,%6,%7}, {%8,%9}, {%0,%1,%2,%3};"
        : "+f"(d[0]), "+f"(d[1]), "+f"(d[2]), "+f"(d[3])
        : "r"(a0), "r"(a1), "r"(a2), "r"(a3), "r"(b0), "r"(b1));
}

// ================= zero (stats + pooled + cnt in one launch) =================
__global__ void zero3(float4* sum4, float4* sq4, float4* pool4, float4* cnt4,
                      int pool4n, int cnt4n) {
    int i = blockIdx.x * blockDim.x + threadIdx.x;
    if (i < pool4n) pool4[i] = make_float4(0.f, 0.f, 0.f, 0.f);
    if (i < cnt4n) cnt4[i] = make_float4(0.f, 0.f, 0.f, 0.f);
    if (i < 3 * DH / 4) {
        sum4[i] = make_float4(0.f, 0.f, 0.f, 0.f);
        sq4[i] = make_float4(0.f, 0.f, 0.f, 0.f);
    }
}

// ================= CSR build =================
__global__ void hist_k(const int* __restrict__ dst, int* __restrict__ cnt, int nE) {
    int i = blockIdx.x * blockDim.x + threadIdx.x;
    if (i < nE) atomicAdd(&cnt[dst[i]], 1);
}
__global__ void scan_block(const int* __restrict__ cnt, int* __restrict__ excl,
                           int* __restrict__ bsum, int n) {
    __shared__ int sm[1024];
    int i = blockIdx.x * 1024 + threadIdx.x;
    int v = (i < n) ? cnt[i] : 0;
    sm[threadIdx.x] = v;
    __syncthreads();
    for (int off = 1; off < 1024; off <<= 1) {
        int t = (threadIdx.x >= off) ? sm[threadIdx.x - off] : 0;
        __syncthreads();
        sm[threadIdx.x] += t;
        __syncthreads();
    }
    if (i < n) excl[i] = sm[threadIdx.x] - v;
    if (threadIdx.x == 1023) bsum[blockIdx.x] = sm[1023];
}
__global__ void __launch_bounds__(256) add_off2(
    int* __restrict__ rowptr, const int* __restrict__ bsum,
    int* __restrict__ cursor, int n, int nE, int nb) {
    __shared__ int soff;
    int t = threadIdx.x;
    int v = (t < nb && t < blockIdx.x) ? bsum[t] : 0;
#pragma unroll
    for (int off = 16; off > 0; off >>= 1) v += __shfl_xor_sync(0xffffffff, v, off);
    __shared__ int warpsum[8];
    if ((t & 31) == 0) warpsum[t >> 5] = v;
    __syncthreads();
    if (t == 0) {
        int s = 0;
#pragma unroll
        for (int w = 0; w < 8; w++) s += warpsum[w];
        soff = s;
    }
    __syncthreads();
    int base = blockIdx.x * 1024;
#pragma unroll
    for (int it = 0; it < 4; it++) {
        int i = base + it * 256 + t;
        if (i < n) {
            int val = rowptr[i] + soff;
            rowptr[i] = val;
            cursor[i] = val;
        }
    }
    if (blockIdx.x == 0 && t == 0) rowptr[n] = nE;
}
__global__ void scatter_k(const int* __restrict__ src, const int* __restrict__ dst,
                          int* __restrict__ cursor, int* __restrict__ csr, int nE) {
    int i = blockIdx.x * blockDim.x + threadIdx.x;
    if (i < nE) {
        int pos = atomicAdd(&cursor[dst[i]], 1);
        csr[pos] = src[i];
    }
}

// ================= gather: h = x[node] + sum_nb x[nb]; interleaved in/out =================
__global__ void __launch_bounds__(256) gather_i(
    const float4* __restrict__ xf, const uint4* __restrict__ xc,
    const int* __restrict__ rowptr, const int* __restrict__ csr,
    uint4* __restrict__ out, int M, int splitIn) {
    int node = blockIdx.x * 8 + (threadIdx.x >> 5);
    if (node >= M) return;
    int lane = threadIdx.x & 31;
    int e0 = __ldg(rowptr + node), e1 = __ldg(rowptr + node + 1);
    float4 acc;
    if (!splitIn) {
        acc = __ldg(xf + (size_t)node * 32 + lane);
        int e = e0;
        for (; e + 16 <= e1; e += 16) {
            int s[16];
#pragma unroll
            for (int u = 0; u < 16; u++) s[u] = __ldg(csr + e + u);
            float4 v[16];
#pragma unroll
            for (int u = 0; u < 16; u++) v[u] = __ldg(xf + (size_t)s[u] * 32 + lane);
#pragma unroll
            for (int u = 0; u < 16; u++) {
                acc.x += v[u].x; acc.y += v[u].y; acc.z += v[u].z; acc.w += v[u].w;
            }
        }
        for (; e + 4 <= e1; e += 4) {
            int s[4];
#pragma unroll
            for (int u = 0; u < 4; u++) s[u] = __ldg(csr + e + u);
            float4 v[4];
#pragma unroll
            for (int u = 0; u < 4; u++) v[u] = __ldg(xf + (size_t)s[u] * 32 + lane);
#pragma unroll
            for (int u = 0; u < 4; u++) {
                acc.x += v[u].x; acc.y += v[u].y; acc.z += v[u].z; acc.w += v[u].w;
            }
        }
        for (; e < e1; e++) {
            int s = __ldg(csr + e);
            float4 v = __ldg(xf + (size_t)s * 32 + lane);
            acc.x += v.x; acc.y += v.y; acc.z += v.z; acc.w += v.w;
        }
    } else {
        acc = dec4(__ldg(xc + (size_t)node * 32 + lane));
        int e = e0;
        for (; e + 16 <= e1; e += 16) {
            int s[16];
#pragma unroll
            for (int u = 0; u < 16; u++) s[u] = __ldg(csr + e + u);
            uint4 w[16];
#pragma unroll
            for (int u = 0; u < 16; u++) w[u] = __ldg(xc + (size_t)s[u] * 32 + lane);
#pragma unroll
            for (int u = 0; u < 16; u++) {
                float4 v = dec4(w[u]);
                acc.x += v.x; acc.y += v.y; acc.z += v.z; acc.w += v.w;
            }
        }
        for (; e + 4 <= e1; e += 4) {
            int s[4];
#pragma unroll
            for (int u = 0; u < 4; u++) s[u] = __ldg(csr + e + u);
            uint4 w[4];
#pragma unroll
            for (int u = 0; u < 4; u++) w[u] = __ldg(xc + (size_t)s[u] * 32 + lane);
#pragma unroll
            for (int u = 0; u < 4; u++) {
                float4 v = dec4(w[u]);
                acc.x += v.x; acc.y += v.y; acc.z += v.z; acc.w += v.w;
            }
        }
        for (; e < e1; e++) {
            int s = __ldg(csr + e);
            float4 v = dec4(__ldg(xc + (size_t)s * 32 + lane));
            acc.x += v.x; acc.y += v.y; acc.z += v.z; acc.w += v.w;
        }
    }
    out[(size_t)node * 32 + lane] = enc4(acc);
}

// ================= W1 prep: all 3 layers in one launch =================
__global__ void __launch_bounds__(128) wprep1all(
    const float* __restrict__ W, uint4* __restrict__ Bpk) {
    int l = blockIdx.x >> 7;
    int n = blockIdx.x & 127, k = threadIdx.x;
    float w = W[(size_t)l * DH * DH + k * DH + n];
    __nv_bfloat16 hi = __float2bfloat16(w);
    __nv_bfloat16 lo = __float2bfloat16(w - __bfloat162float(hi));
    int ks = k >> 4, kr = k & 15;
    int slot = kr >> 3;
    int qid = (kr & 7) >> 1;
    int half = kr & 1;
    int t = n >> 3, gid = n & 7;
    int lane = gid * 4 + qid;
    __nv_bfloat16* p = reinterpret_cast<__nv_bfloat16*>(Bpk + (size_t)l * 4096) +
                       ((size_t)(ks * 16 + t) * 32 + lane) * 8;
    p[slot * 2 + half] = hi;
    p[4 + slot * 2 + half] = lo;
}

// ================= W2 prep with fused BN-affine from raw sums =================
__global__ void __launch_bounds__(128) wprep2f(
    const float* __restrict__ W, const float* __restrict__ bvec,
    const float* __restrict__ sum, const float* __restrict__ sumsq,
    const float* __restrict__ gam, const float* __restrict__ bet,
    float Mf, uint4* __restrict__ Bpk, float* __restrict__ bout) {
    int n = blockIdx.x, k = threadIdx.x;
    float m = sum[k] / Mf;
    float v = sumsq[k] / Mf - m * m;
    float r = rsqrtf(v + BN_EPS);
    float a = gam[k] * r;
    float c = bet[k] - gam[k] * m * r;
    float w = W[k * DH + n];
    float ws = a * w;
    __nv_bfloat16 hi = __float2bfloat16(ws);
    __nv_bfloat16 lo = __float2bfloat16(ws - __bfloat162float(hi));
    int ks = k >> 4, kr = k & 15;
    int slot = kr >> 3;
    int qid = (kr & 7) >> 1;
    int half = kr & 1;
    int t = n >> 3, gid = n & 7;
    int lane = gid * 4 + qid;
    __nv_bfloat16* p = reinterpret_cast<__nv_bfloat16*>(Bpk) +
                       ((size_t)(ks * 16 + t) * 32 + lane) * 8;
    p[slot * 2 + half] = hi;
    p[4 + slot * 2 + half] = lo;
    __shared__ float red[DH];
    red[k] = c * w;
    __syncthreads();
    for (int off = 64; off > 0; off >>= 1) {
        if (k < off) red[k] += red[k + off];
        __syncthreads();
    }
    if (k == 0) bout[n] = bvec[n] + red[0];
}

// ================= smem layout (256-row tiles, persistent, warp-autonomous) =================
#define ASW 68
#define A_ROWS 256
#define SM_AL_OFF (A_ROWS * ASW * 4)       // 69632
#define SM_B_OFF (2 * A_ROWS * ASW * 4)    // 139264
#define SM_BIAS_OFF (SM_B_OFF + 65536)     // 204800
#define SM_STAT_OFF (SM_BIAS_OFF + 512)    // 205312
#define GEMM_SMEM (SM_STAT_OFF + 8192)     // 213504

// per-warp A staging: unconditional (buffers padded to N_PAD rows)
__device__ __forceinline__ void stage_warp_A(const uint4* __restrict__ A,
                                             uint32_t* Ash, uint32_t* Asl,
                                             int warp, int lane, int row0) {
    int m0 = warp * 32;
#pragma unroll
    for (int i = 0; i < 32; i++) {
        int r = m0 + i;
        uint4 v = __ldg(A + (size_t)(row0 + r) * 32 + lane);
        *(uint2*)(Ash + r * ASW + 2 * lane) = make_uint2(v.x, v.z);
        *(uint2*)(Asl + r * ASW + 2 * lane) = make_uint2(v.y, v.w);
    }
}

__device__ __forceinline__ void mainloop(
    const uint32_t* Ash, const uint32_t* Asl, const uint4* Bs,
    int warp, int lane, float acc[2][16][4]) {
    int m0 = warp * 32;
    int gid = lane >> 2, qid = lane & 3;
#pragma unroll
    for (int mt = 0; mt < 2; mt++)
#pragma unroll
        for (int t = 0; t < 16; t++)
#pragma unroll
            for (int j = 0; j < 4; j++) acc[mt][t][j] = 0.f;

    const uint32_t *rh0[2], *rh1[2], *rl0[2], *rl1[2];
#pragma unroll
    for (int mt = 0; mt < 2; mt++) {
        rh0[mt] = Ash + (m0 + 16 * mt + gid) * ASW;
        rh1[mt] = Ash + (m0 + 16 * mt + gid + 8) * ASW;
        rl0[mt] = Asl + (m0 + 16 * mt + gid) * ASW;
        rl1[mt] = Asl + (m0 + 16 * mt + gid + 8) * ASW;
    }
#pragma unroll
    for (int ks = 0; ks < 8; ks++) {
        int kb = ks * 8 + qid;
        uint32_t Ahf[2][4], Alf[2][4];
#pragma unroll
        for (int mt = 0; mt < 2; mt++) {
            Ahf[mt][0] = rh0[mt][kb]; Ahf[mt][1] = rh1[mt][kb];
            Ahf[mt][2] = rh0[mt][kb + 4]; Ahf[mt][3] = rh1[mt][kb + 4];
            Alf[mt][0] = rl0[mt][kb]; Alf[mt][1] = rl1[mt][kb];
            Alf[mt][2] = rl0[mt][kb + 4]; Alf[mt][3] = rl1[mt][kb + 4];
        }
        const uint4* bp = Bs + ks * 512 + lane;
#pragma unroll
        for (int t = 0; t < 16; t++) {
            uint4 bv = bp[t * 32];
#pragma unroll
            for (int mt = 0; mt < 2; mt++) {
                mma_bf16(acc[mt][t], Ahf[mt][0], Ahf[mt][1], Ahf[mt][2], Ahf[mt][3], bv.x, bv.y);
                mma_bf16(acc[mt][t], Ahf[mt][0], Ahf[mt][1], Ahf[mt][2], Ahf[mt][3], bv.z, bv.w);
                mma_bf16(acc[mt][t], Alf[mt][0], Alf[mt][1], Alf[mt][2], Alf[mt][3], bv.x, bv.y);
            }
        }
    }
}

__device__ __forceinline__ void store_pair(uint32_t* orow, int j, float v0, float v1) {
    __nv_bfloat162 H = __floats2bfloat162_rn(v0, v1);
    float2 f = __bfloat1622float2(H);
    __nv_bfloat162 L = __floats2bfloat162_rn(v0 - f.x, v1 - f.y);
    *(uint2*)(orow + 2 * j) = make_uint2(bf2bits(H), bf2bits(L));
}

// ================= GEMM1 persistent warp-autonomous: + leaky + out + fused stats =================
__global__ void __launch_bounds__(256, 1) gemm1_stats(
    const uint4* __restrict__ A, const uint4* __restrict__ Bpk,
    const float* __restrict__ bias, uint32_t* __restrict__ out,
    float* __restrict__ gsum, float* __restrict__ gsq, int M, int nTiles) {
    extern __shared__ char smem[];
    uint32_t* Ash = (uint32_t*)smem;
    uint32_t* Asl = (uint32_t*)(smem + SM_AL_OFF);
    uint4* Bs = (uint4*)(smem + SM_B_OFF);
    float* sb = (float*)(smem + SM_BIAS_OFF);
    float* wstat = (float*)(smem + SM_STAT_OFF);
    int tid = threadIdx.x;
    int warp = tid >> 5, lane = tid & 31;
    int gid = lane >> 2, qid = lane & 3;

    if (tid < 128) sb[tid] = bias[tid];
    float* mystat = wstat + warp * 256;
#pragma unroll
    for (int i = lane; i < 256; i += 32) mystat[i] = 0.f;
#pragma unroll
    for (int it = 0; it < 16; it++) Bs[it * 256 + tid] = __ldg(Bpk + it * 256 + tid);
    __syncthreads();

    for (int tile = blockIdx.x; tile < nTiles; tile += NSM) {
        int row0 = tile << 8;
        __syncwarp();
        stage_warp_A(A, Ash, Asl, warp, lane, row0);
        __syncwarp();
        float acc[2][16][4];
        mainloop(Ash, Asl, Bs, warp, lane, acc);

        float cs[32], cq[32];
#pragma unroll
        for (int i = 0; i < 32; i++) { cs[i] = 0.f; cq[i] = 0.f; }
#pragma unroll
        for (int mt = 0; mt < 2; mt++) {
            int r0 = row0 + warp * 32 + 16 * mt + gid;
            int r1 = r0 + 8;
            uint32_t* orow0 = out + (size_t)r0 * 128;
            uint32_t* orow1 = out + (size_t)r1 * 128;
            bool in0 = (r0 < M), in1 = (r1 < M);
#pragma unroll
            for (int t = 0; t < 16; t++) {
                int c = t * 8 + qid * 2;
                int j = t * 4 + qid;
                float b0 = sb[c], b1 = sb[c + 1];
                float v00 = leaky(acc[mt][t][0] + b0);
                float v01 = leaky(acc[mt][t][1] + b1);
                float v10 = leaky(acc[mt][t][2] + b0);
                float v11 = leaky(acc[mt][t][3] + b1);
                store_pair(orow0, j, v00, v01);   // padded rows: harmless garbage
                store_pair(orow1, j, v10, v11);
                if (!in0) { v00 = 0.f; v01 = 0.f; }
                if (!in1) { v10 = 0.f; v11 = 0.f; }
                cs[2 * t] += v00 + v10;
                cs[2 * t + 1] += v01 + v11;
                cq[2 * t] += v00 * v00 + v10 * v10;
                cq[2 * t + 1] += v01 * v01 + v11 * v11;
            }
        }
#pragma unroll
        for (int i = 0; i < 32; i++) {
#pragma unroll
            for (int off = 4; off < 32; off <<= 1) {
                cs[i] += __shfl_xor_sync(0xffffffff, cs[i], off);
                cq[i] += __shfl_xor_sync(0xffffffff, cq[i], off);
            }
        }
        if (lane < 4) {
#pragma unroll
            for (int t = 0; t < 16; t++) {
                int c = t * 8 + lane * 2;
                mystat[c] += cs[2 * t];
                mystat[c + 1] += cs[2 * t + 1];
                mystat[128 + c] += cq[2 * t];
                mystat[128 + c + 1] += cq[2 * t + 1];
            }
        }
    }
    __syncthreads();
    if (tid < 128) {
        float s = 0.f;
#pragma unroll
        for (int w = 0; w < 8; w++) s += wstat[w * 256 + tid];
        atomicAdd(&gsum[tid], s);
    } else {
        int c = tid - 128;
        float q = 0.f;
#pragma unroll
        for (int w = 0; w < 8; w++) q += wstat[w * 256 + 128 + c];
        atomicAdd(&gsq[c], q);
    }
}

// ================= GEMM2 persistent warp-autonomous: + leaky; mode0: store; mode1: pool =================
__global__ void __launch_bounds__(256, 1) gemm2_pool(
    const uint4* __restrict__ A, const uint4* __restrict__ Bpk,
    const float* __restrict__ bias, uint32_t* __restrict__ out,
    const int* __restrict__ batch, float* __restrict__ pooled,
    int M, int nTiles, int doPool) {
    extern __shared__ char smem[];
    uint32_t* Ash = (uint32_t*)smem;
    uint32_t* Asl = (uint32_t*)(smem + SM_AL_OFF);
    uint4* Bs = (uint4*)(smem + SM_B_OFF);
    float* sb = (float*)(smem + SM_BIAS_OFF);
    int tid = threadIdx.x;
    int warp = tid >> 5, lane = tid & 31;
    int gid = lane >> 2, qid = lane & 3;

    if (tid < 128) sb[tid] = bias[tid];
#pragma unroll
    for (int it = 0; it < 16; it++) Bs[it * 256 + tid] = __ldg(Bpk + it * 256 + tid);
    __syncthreads();

    for (int tile = blockIdx.x; tile < nTiles; tile += NSM) {
        int row0 = tile << 8;
        __syncwarp();
        stage_warp_A(A, Ash, Asl, warp, lane, row0);
        __syncwarp();
        float acc[2][16][4];
        mainloop(Ash, Asl, Bs, warp, lane, acc);

        if (!doPool) {
#pragma unroll
            for (int mt = 0; mt < 2; mt++) {
                int r0 = row0 + warp * 32 + 16 * mt + gid;
                int r1 = r0 + 8;
                uint32_t* orow0 = out + (size_t)r0 * 128;
                uint32_t* orow1 = out + (size_t)r1 * 128;
#pragma unroll
                for (int t = 0; t < 16; t++) {
                    int c = t * 8 + qid * 2;
                    int j = t * 4 + qid;
                    float b0 = sb[c], b1 = sb[c + 1];
                    store_pair(orow0, j, leaky(acc[mt][t][0] + b0), leaky(acc[mt][t][1] + b1));
                    store_pair(orow1, j, leaky(acc[mt][t][2] + b0), leaky(acc[mt][t][3] + b1));
                }
            }
        } else {
#pragma unroll
            for (int mt = 0; mt < 2; mt++) {
                int r0 = row0 + warp * 32 + 16 * mt + gid;
                int r1 = r0 + 8;
                int b0g = (r0 < M) ? __ldg(batch + r0) : 0;
                int b1g = (r1 < M) ? __ldg(batch + r1) : 0;
#pragma unroll
                for (int t = 0; t < 16; t++) {
                    int c = t * 8 + qid * 2;
                    float b0 = sb[c], b1 = sb[c + 1];
                    if (r0 < M)
                        red_add_v2(pooled + (size_t)b0g * DH + c,
                                   leaky(acc[mt][t][0] + b0), leaky(acc[mt][t][1] + b1));
                    if (r1 < M)
                        red_add_v2(pooled + (size_t)b1g * DH + c,
                                   leaky(acc[mt][t][2] + b0), leaky(acc[mt][t][3] + b1));
                }
            }
        }
    }
}

// ================= small column stats (pooled / h1) =================
__global__ void colstats(const float* __restrict__ data, int rows, int cols,
                         const float* __restrict__ g, const float* __restrict__ b,
                         float* __restrict__ oa, float* __restrict__ oc) {
    int col = blockIdx.x;
    int t = threadIdx.x;
    float s = 0.f, q = 0.f;
    for (int r = t; r < rows; r += blockDim.x) {
        float v = data[(size_t)r * cols + col];
        s += v; q += v * v;
    }
    __shared__ float ss[256], qq[256];
    ss[t] = s; qq[t] = q;
    __syncthreads();
    for (int off = 128; off > 0; off >>= 1) {
        if (t < off) { ss[t] += ss[t + off]; qq[t] += qq[t + off]; }
        __syncthreads();
    }
    if (t == 0) {
        float m = ss[0] / rows;
        float v = qq[0] / rows - m * m;
        float r = rsqrtf(v + BN_EPS);
        oa[col] = g[col] * r;
        oc[col] = b[col] - g[col] * m * r;
    }
}

// ================= head =================
__global__ void __launch_bounds__(64) head1(
    const float* __restrict__ pooled, const float* __restrict__ pa, const float* __restrict__ pc,
    const float* __restrict__ fcW, const float* __restrict__ fcb,
    const float* __restrict__ feats,
    const float* __restrict__ cW1, const float* __restrict__ cb1,
    const float* __restrict__ cW2, const float* __restrict__ cb2,
    const float* __restrict__ fW1, const float* __restrict__ fb1,
    float* __restrict__ h1out) {
    int g = blockIdx.x;
    int j = threadIdx.x;
    __shared__ float cat[DLAT + 8];
    float o = fcb[j];
    const float* pr = pooled + (size_t)g * DH;
    for (int k = 0; k < DH; k++) o += (pr[k] * pa[k] + pc[k]) * fcW[k * DLAT + j];
    cat[j] = o;
    if (j < 8) {
        float c1[8];
#pragma unroll
        for (int i = 0; i < 8; i++) {
            float a = cb1[i];
#pragma unroll
            for (int m = 0; m < NCOND; m++) a += feats[g * NCOND + m] * cW1[m * 8 + i];
            c1[i] = fmaxf(a, 0.f);
        }
        float o2 = cb2[j];
#pragma unroll
        for (int i = 0; i < 8; i++) o2 += c1[i] * cW2[i * 8 + j];
        cat[DLAT + j] = o2;
    }
    __syncthreads();
    float h = fb1[j];
    for (int k = 0; k < DLAT + 8; k++) h += cat[k] * fW1[k * DLAT + j];
    h1out[(size_t)g * DLAT + j] = leaky(h);
}

__global__ void __launch_bounds__(64) head2(
    const float* __restrict__ h1, const float* __restrict__ fa, const float* __restrict__ fc,
    const float* __restrict__ fW2, const float* __restrict__ fb2,
    float* __restrict__ out) {
    int g = blockIdx.x;
    int j = threadIdx.x;
    __shared__ float hn[DLAT];
    hn[j] = h1[(size_t)g * DLAT + j] * fa[j] + fc[j];
    __syncthreads();
    float o = fb2[j];
    for (int k = 0; k < DLAT; k++) o += hn[k] * fW2[k * DLAT + j];
    out[(size_t)g * DLAT + j] = o;
}

// ================= launch =================
extern "C" void kernel_launch(void* const* d_in, const int* in_sizes, int n_in,
                              void* d_out, int out_size) {
    const float* x      = (const float*)d_in[0];
    const int*   ei     = (const int*)d_in[1];
    const int*   batch  = (const int*)d_in[2];
    const float* feats  = (const float*)d_in[3];
    const float* convW1 = (const float*)d_in[4];
    const float* convb1 = (const float*)d_in[5];
    const float* convg1 = (const float*)d_in[6];
    const float* convbb1= (const float*)d_in[7];
    const float* convW2 = (const float*)d_in[8];
    const float* convb2 = (const float*)d_in[9];
    const float* bng    = (const float*)d_in[10];
    const float* bnb    = (const float*)d_in[11];
    const float* fcW    = (const float*)d_in[12];
    const float* fcb    = (const float*)d_in[13];
    const float* cW1    = (const float*)d_in[14];
    const float* cb1    = (const float*)d_in[15];
    const float* cW2    = (const float*)d_in[16];
    const float* cb2    = (const float*)d_in[17];
    const float* fW1    = (const float*)d_in[18];
    const float* fb1    = (const float*)d_in[19];
    const float* fg     = (const float*)d_in[20];
    const float* fb_    = (const float*)d_in[21];
    const float* fW2    = (const float*)d_in[22];
    const float* fb2    = (const float*)d_in[23];
    float* dout = (float*)d_out;

    int nE = in_sizes[1] / 2;
    const int* src = ei;
    const int* dst = ei + nE;
    int M = in_sizes[0] / DH;
    int G = in_sizes[3] / NCOND;

    uint4 *p_a, *p_h, *p_x, *p_Bpk1, *p_Bpk2;
    float *p_bias, *p_sum, *p_sq, *p_pool, *p_pa, *p_pc, *p_h1, *p_fa, *p_fc;
    int *p_cnt, *p_rowptr, *p_bsum, *p_csr;
    cudaGetSymbolAddress((void**)&p_a, g_a);
    cudaGetSymbolAddress((void**)&p_h, g_h);
    cudaGetSymbolAddress((void**)&p_x, g_x);
    cudaGetSymbolAddress((void**)&p_Bpk1, g_Bpk1);
    cudaGetSymbolAddress((void**)&p_Bpk2, g_Bpk2);
    cudaGetSymbolAddress((void**)&p_bias, g_bias);
    cudaGetSymbolAddress((void**)&p_cnt, g_cnt);
    cudaGetSymbolAddress((void**)&p_rowptr, g_rowptr);
    cudaGetSymbolAddress((void**)&p_bsum, g_bsum);
    cudaGetSymbolAddress((void**)&p_csr, g_csr);
    cudaGetSymbolAddress((void**)&p_sum, g_sum);
    cudaGetSymbolAddress((void**)&p_sq, g_sumsq);
    cudaGetSymbolAddress((void**)&p_pool, g_pooled);
    cudaGetSymbolAddress((void**)&p_pa, g_pa);
    cudaGetSymbolAddress((void**)&p_pc, g_pc);
    cudaGetSymbolAddress((void**)&p_h1, g_h1);
    cudaGetSymbolAddress((void**)&p_fa, g_fa);
    cudaGetSymbolAddress((void**)&p_fc, g_fc);

    cudaFuncSetAttribute(gemm1_stats, cudaFuncAttributeMaxDynamicSharedMemorySize, GEMM_SMEM);
    cudaFuncSetAttribute(gemm2_pool, cudaFuncAttributeMaxDynamicSharedMemorySize, GEMM_SMEM);

    // ---- zero stats + pooled + cnt in one launch ----
    int cnt4n = N_NODES / 4;
    int zgrid = (cnt4n > N_GRAPHS * DH / 4 ? cnt4n : N_GRAPHS * DH / 4);
    zero3<<<(zgrid + 255) / 256, 256>>>(
        (float4*)p_sum, (float4*)p_sq, (float4*)p_pool, (float4*)p_cnt,
        N_GRAPHS * DH / 4, cnt4n);

    // ---- CSR build ----
    hist_k<<<(nE + 255) / 256, 256>>>(dst, p_cnt, nE);
    int nb = (M + 1023) / 1024;
    scan_block<<<nb, 1024>>>(p_cnt, p_rowptr, p_bsum, M);
    add_off2<<<nb, 256>>>(p_rowptr, p_bsum, p_cnt, M, nE, nb);
    scatter_k<<<(nE + 255) / 256, 256>>>(src, dst, p_cnt, p_csr, nE);

    // ---- pack all W1 in one launch ----
    wprep1all<<<3 * DH, DH>>>(convW1, p_Bpk1);

    int nTiles = (M + 255) / 256;
    for (int l = 0; l < 3; l++) {
        gather_i<<<(M + 7) / 8, 256>>>(
            (const float4*)x, (const uint4*)p_x, p_rowptr, p_csr, p_a, M, (l == 0) ? 0 : 1);
        gemm1_stats<<<NSM, 256, GEMM_SMEM>>>(
            p_a, p_Bpk1 + (size_t)l * 4096, convb1 + l * DH, (uint32_t*)p_h,
            p_sum + l * DH, p_sq + l * DH, M, nTiles);
        wprep2f<<<DH, DH>>>(convW2 + (size_t)l * DH * DH, convb2 + l * DH,
                            p_sum + l * DH, p_sq + l * DH,
                            convg1 + l * DH, convbb1 + l * DH, (float)M, p_Bpk2, p_bias);
        gemm2_pool<<<NSM, 256, GEMM_SMEM>>>(
            p_h, p_Bpk2, p_bias, (uint32_t*)p_x, batch, p_pool, M, nTiles, (l == 2) ? 1 : 0);
    }

    colstats<<<DH, 256>>>(p_pool, G, DH, bng, bnb, p_pa, p_pc);
    head1<<<G, 64>>>(p_pool, p_pa, p_pc, fcW, fcb, feats, cW1, cb1, cW2, cb2, fW1, fb1, p_h1);
    colstats<<<DLAT, 256>>>(p_h1, G, DLAT, fg, fb_, p_fa, p_fc);
    head2<<<G, 64>>>(p_h1, p_fa, p_fc, fW2, fb2, dout);
}

// round 17
// speedup vs baseline: 1.0983x; 1.0502x over previous
#include <cuda_runtime.h>
#include <cuda_bf16.h>
#include <cstdint>

#define N_NODES 100000
#define N_PAD (N_NODES + 256)
#define N_EDGESC 1600000
#define N_GRAPHS 512
#define DH 128
#define DLAT 64
#define NCOND 7
#define BN_EPS 1e-5f
#define NSM 148

// ================= scratch (device globals; zero-initialized at load) =================
__device__ uint4 g_a[N_PAD * 32];        // gather out (interleaved hi/lo) -> gemm1
__device__ uint4 g_h[N_PAD * 32];        // GEMM1 out (interleaved hi/lo) -> gemm2
__device__ float g_x[N_PAD * DH];        // GEMM2 out (fp32) -> next gather
__device__ uint4 g_Bpk1[3 * 128 * 32];   // W1 fragment packs
__device__ uint4 g_Bpk2[128 * 32];       // W2 fragment pack (per layer)
__device__ float g_bias[DH];
__device__ int g_cnt[N_NODES];
__device__ int g_rowptr[N_NODES + 1];
__device__ int g_bsum[128];
__device__ int g_csr[N_EDGESC];
__device__ float g_sum[3 * DH];
__device__ float g_sumsq[3 * DH];
__device__ float g_pooled[N_GRAPHS * DH];
__device__ float g_pa[DH];
__device__ float g_pc[DH];
__device__ float g_h1[N_GRAPHS * DLAT];
__device__ float g_fa[DLAT];
__device__ float g_fc[DLAT];

// ================= helpers =================
__device__ __forceinline__ float leaky(float x) { return fmaxf(x, 0.2f * x); }
__device__ __forceinline__ void red_add_v2(float* p, float a, float b) {
    asm volatile("red.global.add.v2.f32 [%0], {%1,%2};"
                 :: "l"(p), "f"(a), "f"(b) : "memory");
}
__device__ __forceinline__ uint32_t bf2bits(__nv_bfloat162 v) {
    return *reinterpret_cast<uint32_t*>(&v);
}
__device__ __forceinline__ uint4 enc4(float4 a) {
    __nv_bfloat162 H0 = __floats2bfloat162_rn(a.x, a.y);
    __nv_bfloat162 H1 = __floats2bfloat162_rn(a.z, a.w);
    float2 f0 = __bfloat1622float2(H0), f1 = __bfloat1622float2(H1);
    __nv_bfloat162 L0 = __floats2bfloat162_rn(a.x - f0.x, a.y - f0.y);
    __nv_bfloat162 L1 = __floats2bfloat162_rn(a.z - f1.x, a.w - f1.y);
    return make_uint4(bf2bits(H0), bf2bits(L0), bf2bits(H1), bf2bits(L1));
}
__device__ __forceinline__ void mma_bf16(float* d, uint32_t a0, uint32_t a1,
                                         uint32_t a2, uint32_t a3,
                                         uint32_t b0, uint32_t b1) {
    asm volatile(
        "mma.sync.aligned.m16n8k16.row.col.f32.bf16.bf16.f32 "
        "{%0,%1,%2,%3}, {%4,%5,%6,%7}, {%8,%9}, {%0,%1,%2,%3};"
        : "+f"(d[0]), "+f"(d[1]), "+f"(d[2]), "+f"(d[3])
        : "r"(a0), "r"(a1), "r"(a2), "r"(a3), "r"(b0), "r"(b1));
}

// ================= zero (stats + pooled + cnt in one launch) =================
__global__ void zero3(float4* sum4, float4* sq4, float4* pool4, float4* cnt4,
                      int pool4n, int cnt4n) {
    int i = blockIdx.x * blockDim.x + threadIdx.x;
    if (i < pool4n) pool4[i] = make_float4(0.f, 0.f, 0.f, 0.f);
    if (i < cnt4n) cnt4[i] = make_float4(0.f, 0.f, 0.f, 0.f);
    if (i < 3 * DH / 4) {
        sum4[i] = make_float4(0.f, 0.f, 0.f, 0.f);
        sq4[i] = make_float4(0.f, 0.f, 0.f, 0.f);
    }
}

// ================= CSR build =================
__global__ void hist_k(const int* __restrict__ dst, int* __restrict__ cnt, int nE) {
    int i = blockIdx.x * blockDim.x + threadIdx.x;
    if (i < nE) atomicAdd(&cnt[dst[i]], 1);
}
__global__ void scan_block(const int* __restrict__ cnt, int* __restrict__ excl,
                           int* __restrict__ bsum, int n) {
    __shared__ int sm[1024];
    int i = blockIdx.x * 1024 + threadIdx.x;
    int v = (i < n) ? cnt[i] : 0;
    sm[threadIdx.x] = v;
    __syncthreads();
    for (int off = 1; off < 1024; off <<= 1) {
        int t = (threadIdx.x >= off) ? sm[threadIdx.x - off] : 0;
        __syncthreads();
        sm[threadIdx.x] += t;
        __syncthreads();
    }
    if (i < n) excl[i] = sm[threadIdx.x] - v;
    if (threadIdx.x == 1023) bsum[blockIdx.x] = sm[1023];
}
__global__ void __launch_bounds__(256) add_off2(
    int* __restrict__ rowptr, const int* __restrict__ bsum,
    int* __restrict__ cursor, int n, int nE, int nb) {
    __shared__ int soff;
    int t = threadIdx.x;
    int v = (t < nb && t < blockIdx.x) ? bsum[t] : 0;
#pragma unroll
    for (int off = 16; off > 0; off >>= 1) v += __shfl_xor_sync(0xffffffff, v, off);
    __shared__ int warpsum[8];
    if ((t & 31) == 0) warpsum[t >> 5] = v;
    __syncthreads();
    if (t == 0) {
        int s = 0;
#pragma unroll
        for (int w = 0; w < 8; w++) s += warpsum[w];
        soff = s;
    }
    __syncthreads();
    int base = blockIdx.x * 1024;
#pragma unroll
    for (int it = 0; it < 4; it++) {
        int i = base + it * 256 + t;
        if (i < n) {
            int val = rowptr[i] + soff;
            rowptr[i] = val;
            cursor[i] = val;
        }
    }
    if (blockIdx.x == 0 && t == 0) rowptr[n] = nE;
}
__global__ void scatter_k(const int* __restrict__ src, const int* __restrict__ dst,
                          int* __restrict__ cursor, int* __restrict__ csr, int nE) {
    int i = blockIdx.x * blockDim.x + threadIdx.x;
    if (i < nE) {
        int pos = atomicAdd(&cursor[dst[i]], 1);
        csr[pos] = src[i];
    }
}

// ================= gather: h = x[node] + sum_nb x[nb]; fp32 in, packed out =================
__global__ void __launch_bounds__(256) gather_f(
    const float4* __restrict__ xf,
    const int* __restrict__ rowptr, const int* __restrict__ csr,
    uint4* __restrict__ out, int M) {
    int node = blockIdx.x * 8 + (threadIdx.x >> 5);
    if (node >= M) return;
    int lane = threadIdx.x & 31;
    int e0 = __ldg(rowptr + node), e1 = __ldg(rowptr + node + 1);
    float4 acc = __ldg(xf + (size_t)node * 32 + lane);
    int e = e0;
    for (; e + 16 <= e1; e += 16) {
        int s[16];
#pragma unroll
        for (int u = 0; u < 16; u++) s[u] = __ldg(csr + e + u);
        float4 v[16];
#pragma unroll
        for (int u = 0; u < 16; u++) v[u] = __ldg(xf + (size_t)s[u] * 32 + lane);
#pragma unroll
        for (int u = 0; u < 16; u++) {
            acc.x += v[u].x; acc.y += v[u].y; acc.z += v[u].z; acc.w += v[u].w;
        }
    }
    for (; e + 4 <= e1; e += 4) {
        int s[4];
#pragma unroll
        for (int u = 0; u < 4; u++) s[u] = __ldg(csr + e + u);
        float4 v[4];
#pragma unroll
        for (int u = 0; u < 4; u++) v[u] = __ldg(xf + (size_t)s[u] * 32 + lane);
#pragma unroll
        for (int u = 0; u < 4; u++) {
            acc.x += v[u].x; acc.y += v[u].y; acc.z += v[u].z; acc.w += v[u].w;
        }
    }
    for (; e < e1; e++) {
        int s = __ldg(csr + e);
        float4 v = __ldg(xf + (size_t)s * 32 + lane);
        acc.x += v.x; acc.y += v.y; acc.z += v.z; acc.w += v.w;
    }
    out[(size_t)node * 32 + lane] = enc4(acc);
}

// ================= W1 prep: all 3 layers in one launch =================
__global__ void __launch_bounds__(128) wprep1all(
    const float* __restrict__ W, uint4* __restrict__ Bpk) {
    int l = blockIdx.x >> 7;
    int n = blockIdx.x & 127, k = threadIdx.x;
    float w = W[(size_t)l * DH * DH + k * DH + n];
    __nv_bfloat16 hi = __float2bfloat16(w);
    __nv_bfloat16 lo = __float2bfloat16(w - __bfloat162float(hi));
    int ks = k >> 4, kr = k & 15;
    int slot = kr >> 3;
    int qid = (kr & 7) >> 1;
    int half = kr & 1;
    int t = n >> 3, gid = n & 7;
    int lane = gid * 4 + qid;
    __nv_bfloat16* p = reinterpret_cast<__nv_bfloat16*>(Bpk + (size_t)l * 4096) +
                       ((size_t)(ks * 16 + t) * 32 + lane) * 8;
    p[slot * 2 + half] = hi;
    p[4 + slot * 2 + half] = lo;
}

// ================= W2 prep with fused BN-affine from raw sums =================
__global__ void __launch_bounds__(128) wprep2f(
    const float* __restrict__ W, const float* __restrict__ bvec,
    const float* __restrict__ sum, const float* __restrict__ sumsq,
    const float* __restrict__ gam, const float* __restrict__ bet,
    float Mf, uint4* __restrict__ Bpk, float* __restrict__ bout) {
    int n = blockIdx.x, k = threadIdx.x;
    float m = sum[k] / Mf;
    float v = sumsq[k] / Mf - m * m;
    float r = rsqrtf(v + BN_EPS);
    float a = gam[k] * r;
    float c = bet[k] - gam[k] * m * r;
    float w = W[k * DH + n];
    float ws = a * w;
    __nv_bfloat16 hi = __float2bfloat16(ws);
    __nv_bfloat16 lo = __float2bfloat16(ws - __bfloat162float(hi));
    int ks = k >> 4, kr = k & 15;
    int slot = kr >> 3;
    int qid = (kr & 7) >> 1;
    int half = kr & 1;
    int t = n >> 3, gid = n & 7;
    int lane = gid * 4 + qid;
    __nv_bfloat16* p = reinterpret_cast<__nv_bfloat16*>(Bpk) +
                       ((size_t)(ks * 16 + t) * 32 + lane) * 8;
    p[slot * 2 + half] = hi;
    p[4 + slot * 2 + half] = lo;
    __shared__ float red[DH];
    red[k] = c * w;
    __syncthreads();
    for (int off = 64; off > 0; off >>= 1) {
        if (k < off) red[k] += red[k + off];
        __syncthreads();
    }
    if (k == 0) bout[n] = bvec[n] + red[0];
}

// ================= smem layout (256-row tiles, persistent, warp-autonomous) =================
#define ASW 68
#define A_ROWS 256
#define SM_AL_OFF (A_ROWS * ASW * 4)       // 69632
#define SM_B_OFF (2 * A_ROWS * ASW * 4)    // 139264
#define SM_BIAS_OFF (SM_B_OFF + 65536)     // 204800
#define SM_STAT_OFF (SM_BIAS_OFF + 512)    // 205312
#define GEMM_SMEM (SM_STAT_OFF + 8192)     // 213504

// per-warp A staging: unconditional (buffers padded to N_PAD rows)
__device__ __forceinline__ void stage_warp_A(const uint4* __restrict__ A,
                                             uint32_t* Ash, uint32_t* Asl,
                                             int warp, int lane, int row0) {
    int m0 = warp * 32;
#pragma unroll
    for (int i = 0; i < 32; i++) {
        int r = m0 + i;
        uint4 v = __ldg(A + (size_t)(row0 + r) * 32 + lane);
        *(uint2*)(Ash + r * ASW + 2 * lane) = make_uint2(v.x, v.z);
        *(uint2*)(Asl + r * ASW + 2 * lane) = make_uint2(v.y, v.w);
    }
}

__device__ __forceinline__ void mainloop(
    const uint32_t* Ash, const uint32_t* Asl, const uint4* Bs,
    int warp, int lane, float acc[2][16][4]) {
    int m0 = warp * 32;
    int gid = lane >> 2, qid = lane & 3;
#pragma unroll
    for (int mt = 0; mt < 2; mt++)
#pragma unroll
        for (int t = 0; t < 16; t++)
#pragma unroll
            for (int j = 0; j < 4; j++) acc[mt][t][j] = 0.f;

    const uint32_t *rh0[2], *rh1[2], *rl0[2], *rl1[2];
#pragma unroll
    for (int mt = 0; mt < 2; mt++) {
        rh0[mt] = Ash + (m0 + 16 * mt + gid) * ASW;
        rh1[mt] = Ash + (m0 + 16 * mt + gid + 8) * ASW;
        rl0[mt] = Asl + (m0 + 16 * mt + gid) * ASW;
        rl1[mt] = Asl + (m0 + 16 * mt + gid + 8) * ASW;
    }
#pragma unroll
    for (int ks = 0; ks < 8; ks++) {
        int kb = ks * 8 + qid;
        uint32_t Ahf[2][4], Alf[2][4];
#pragma unroll
        for (int mt = 0; mt < 2; mt++) {
            Ahf[mt][0] = rh0[mt][kb]; Ahf[mt][1] = rh1[mt][kb];
            Ahf[mt][2] = rh0[mt][kb + 4]; Ahf[mt][3] = rh1[mt][kb + 4];
            Alf[mt][0] = rl0[mt][kb]; Alf[mt][1] = rl1[mt][kb];
            Alf[mt][2] = rl0[mt][kb + 4]; Alf[mt][3] = rl1[mt][kb + 4];
        }
        const uint4* bp = Bs + ks * 512 + lane;
#pragma unroll
        for (int t = 0; t < 16; t++) {
            uint4 bv = bp[t * 32];
#pragma unroll
            for (int mt = 0; mt < 2; mt++) {
                mma_bf16(acc[mt][t], Ahf[mt][0], Ahf[mt][1], Ahf[mt][2], Ahf[mt][3], bv.x, bv.y);
                mma_bf16(acc[mt][t], Ahf[mt][0], Ahf[mt][1], Ahf[mt][2], Ahf[mt][3], bv.z, bv.w);
                mma_bf16(acc[mt][t], Alf[mt][0], Alf[mt][1], Alf[mt][2], Alf[mt][3], bv.x, bv.y);
            }
        }
    }
}

__device__ __forceinline__ void store_pair(uint32_t* orow, int j, float v0, float v1) {
    __nv_bfloat162 H = __floats2bfloat162_rn(v0, v1);
    float2 f = __bfloat1622float2(H);
    __nv_bfloat162 L = __floats2bfloat162_rn(v0 - f.x, v1 - f.y);
    *(uint2*)(orow + 2 * j) = make_uint2(bf2bits(H), bf2bits(L));
}

// ================= GEMM1 persistent warp-autonomous: + leaky + packed out + fused stats =================
__global__ void __launch_bounds__(256, 1) gemm1_stats(
    const uint4* __restrict__ A, const uint4* __restrict__ Bpk,
    const float* __restrict__ bias, uint32_t* __restrict__ out,
    float* __restrict__ gsum, float* __restrict__ gsq, int M, int nTiles) {
    extern __shared__ char smem[];
    uint32_t* Ash = (uint32_t*)smem;
    uint32_t* Asl = (uint32_t*)(smem + SM_AL_OFF);
    uint4* Bs = (uint4*)(smem + SM_B_OFF);
    float* sb = (float*)(smem + SM_BIAS_OFF);
    float* wstat = (float*)(smem + SM_STAT_OFF);
    int tid = threadIdx.x;
    int warp = tid >> 5, lane = tid & 31;
    int gid = lane >> 2, qid = lane & 3;

    if (tid < 128) sb[tid] = bias[tid];
    float* mystat = wstat + warp * 256;
#pragma unroll
    for (int i = lane; i < 256; i += 32) mystat[i] = 0.f;
#pragma unroll
    for (int it = 0; it < 16; it++) Bs[it * 256 + tid] = __ldg(Bpk + it * 256 + tid);
    __syncthreads();

    for (int tile = blockIdx.x; tile < nTiles; tile += NSM) {
        int row0 = tile << 8;
        __syncwarp();
        stage_warp_A(A, Ash, Asl, warp, lane, row0);
        __syncwarp();
        float acc[2][16][4];
        mainloop(Ash, Asl, Bs, warp, lane, acc);

        float cs[32], cq[32];
#pragma unroll
        for (int i = 0; i < 32; i++) { cs[i] = 0.f; cq[i] = 0.f; }
#pragma unroll
        for (int mt = 0; mt < 2; mt++) {
            int r0 = row0 + warp * 32 + 16 * mt + gid;
            int r1 = r0 + 8;
            uint32_t* orow0 = out + (size_t)r0 * 128;
            uint32_t* orow1 = out + (size_t)r1 * 128;
            bool in0 = (r0 < M), in1 = (r1 < M);
#pragma unroll
            for (int t = 0; t < 16; t++) {
                int c = t * 8 + qid * 2;
                int j = t * 4 + qid;
                float b0 = sb[c], b1 = sb[c + 1];
                float v00 = leaky(acc[mt][t][0] + b0);
                float v01 = leaky(acc[mt][t][1] + b1);
                float v10 = leaky(acc[mt][t][2] + b0);
                float v11 = leaky(acc[mt][t][3] + b1);
                store_pair(orow0, j, v00, v01);   // padded rows: harmless garbage
                store_pair(orow1, j, v10, v11);
                if (!in0) { v00 = 0.f; v01 = 0.f; }
                if (!in1) { v10 = 0.f; v11 = 0.f; }
                cs[2 * t] += v00 + v10;
                cs[2 * t + 1] += v01 + v11;
                cq[2 * t] += v00 * v00 + v10 * v10;
                cq[2 * t + 1] += v01 * v01 + v11 * v11;
            }
        }
#pragma unroll
        for (int i = 0; i < 32; i++) {
#pragma unroll
            for (int off = 4; off < 32; off <<= 1) {
                cs[i] += __shfl_xor_sync(0xffffffff, cs[i], off);
                cq[i] += __shfl_xor_sync(0xffffffff, cq[i], off);
            }
        }
        if (lane < 4) {
#pragma unroll
            for (int t = 0; t < 16; t++) {
                int c = t * 8 + lane * 2;
                mystat[c] += cs[2 * t];
                mystat[c + 1] += cs[2 * t + 1];
                mystat[128 + c] += cq[2 * t];
                mystat[128 + c + 1] += cq[2 * t + 1];
            }
        }
    }
    __syncthreads();
    if (tid < 128) {
        float s = 0.f;
#pragma unroll
        for (int w = 0; w < 8; w++) s += wstat[w * 256 + tid];
        atomicAdd(&gsum[tid], s);
    } else {
        int c = tid - 128;
        float q = 0.f;
#pragma unroll
        for (int w = 0; w < 8; w++) q += wstat[w * 256 + 128 + c];
        atomicAdd(&gsq[c], q);
    }
}

// ================= GEMM2 persistent warp-autonomous: + leaky; mode0: fp32 store; mode1: pool =================
__global__ void __launch_bounds__(256, 1) gemm2_pool(
    const uint4* __restrict__ A, const uint4* __restrict__ Bpk,
    const float* __restrict__ bias, float* __restrict__ outF,
    const int* __restrict__ batch, float* __restrict__ pooled,
    int M, int nTiles, int doPool) {
    extern __shared__ char smem[];
    uint32_t* Ash = (uint32_t*)smem;
    uint32_t* Asl = (uint32_t*)(smem + SM_AL_OFF);
    uint4* Bs = (uint4*)(smem + SM_B_OFF);
    float* sb = (float*)(smem + SM_BIAS_OFF);
    int tid = threadIdx.x;
    int warp = tid >> 5, lane = tid & 31;
    int gid = lane >> 2, qid = lane & 3;

    if (tid < 128) sb[tid] = bias[tid];
#pragma unroll
    for (int it = 0; it < 16; it++) Bs[it * 256 + tid] = __ldg(Bpk + it * 256 + tid);
    __syncthreads();

    for (int tile = blockIdx.x; tile < nTiles; tile += NSM) {
        int row0 = tile << 8;
        __syncwarp();
        stage_warp_A(A, Ash, Asl, warp, lane, row0);
        __syncwarp();
        float acc[2][16][4];
        mainloop(Ash, Asl, Bs, warp, lane, acc);

        if (!doPool) {
#pragma unroll
            for (int mt = 0; mt < 2; mt++) {
                int r0 = row0 + warp * 32 + 16 * mt + gid;
                int r1 = r0 + 8;
                float* orow0 = outF + (size_t)r0 * DH;
                float* orow1 = outF + (size_t)r1 * DH;
#pragma unroll
                for (int t = 0; t < 16; t++) {
                    int c = t * 8 + qid * 2;
                    float b0 = sb[c], b1 = sb[c + 1];
                    *(float2*)(orow0 + c) =
                        make_float2(leaky(acc[mt][t][0] + b0), leaky(acc[mt][t][1] + b1));
                    *(float2*)(orow1 + c) =
                        make_float2(leaky(acc[mt][t][2] + b0), leaky(acc[mt][t][3] + b1));
                }
            }
        } else {
#pragma unroll
            for (int mt = 0; mt < 2; mt++) {
                int r0 = row0 + warp * 32 + 16 * mt + gid;
                int r1 = r0 + 8;
                int b0g = (r0 < M) ? __ldg(batch + r0) : 0;
                int b1g = (r1 < M) ? __ldg(batch + r1) : 0;
#pragma unroll
                for (int t = 0; t < 16; t++) {
                    int c = t * 8 + qid * 2;
                    float b0 = sb[c], b1 = sb[c + 1];
                    if (r0 < M)
                        red_add_v2(pooled + (size_t)b0g * DH + c,
                                   leaky(acc[mt][t][0] + b0), leaky(acc[mt][t][1] + b1));
                    if (r1 < M)
                        red_add_v2(pooled + (size_t)b1g * DH + c,
                                   leaky(acc[mt][t][2] + b0), leaky(acc[mt][t][3] + b1));
                }
            }
        }
    }
}

// ================= small column stats (pooled / h1) =================
__global__ void colstats(const float* __restrict__ data, int rows, int cols,
                         const float* __restrict__ g, const float* __restrict__ b,
                         float* __restrict__ oa, float* __restrict__ oc) {
    int col = blockIdx.x;
    int t = threadIdx.x;
    float s = 0.f, q = 0.f;
    for (int r = t; r < rows; r += blockDim.x) {
        float v = data[(size_t)r * cols + col];
        s += v; q += v * v;
    }
    __shared__ float ss[256], qq[256];
    ss[t] = s; qq[t] = q;
    __syncthreads();
    for (int off = 128; off > 0; off >>= 1) {
        if (t < off) { ss[t] += ss[t + off]; qq[t] += qq[t + off]; }
        __syncthreads();
    }
    if (t == 0) {
        float m = ss[0] / rows;
        float v = qq[0] / rows - m * m;
        float r = rsqrtf(v + BN_EPS);
        oa[col] = g[col] * r;
        oc[col] = b[col] - g[col] * m * r;
    }
}

// ================= head =================
__global__ void __launch_bounds__(64) head1(
    const float* __restrict__ pooled, const float* __restrict__ pa, const float* __restrict__ pc,
    const float* __restrict__ fcW, const float* __restrict__ fcb,
    const float* __restrict__ feats,
    const float* __restrict__ cW1, const float* __restrict__ cb1,
    const float* __restrict__ cW2, const float* __restrict__ cb2,
    const float* __restrict__ fW1, const float* __restrict__ fb1,
    float* __restrict__ h1out) {
    int g = blockIdx.x;
    int j = threadIdx.x;
    __shared__ float cat[DLAT + 8];
    float o = fcb[j];
    const float* pr = pooled + (size_t)g * DH;
    for (int k = 0; k < DH; k++) o += (pr[k] * pa[k] + pc[k]) * fcW[k * DLAT + j];
    cat[j] = o;
    if (j < 8) {
        float c1[8];
#pragma unroll
        for (int i = 0; i < 8; i++) {
            float a = cb1[i];
#pragma unroll
            for (int m = 0; m < NCOND; m++) a += feats[g * NCOND + m] * cW1[m * 8 + i];
            c1[i] = fmaxf(a, 0.f);
        }
        float o2 = cb2[j];
#pragma unroll
        for (int i = 0; i < 8; i++) o2 += c1[i] * cW2[i * 8 + j];
        cat[DLAT + j] = o2;
    }
    __syncthreads();
    float h = fb1[j];
    for (int k = 0; k < DLAT + 8; k++) h += cat[k] * fW1[k * DLAT + j];
    h1out[(size_t)g * DLAT + j] = leaky(h);
}

__global__ void __launch_bounds__(64) head2(
    const float* __restrict__ h1, const float* __restrict__ fa, const float* __restrict__ fc,
    const float* __restrict__ fW2, const float* __restrict__ fb2,
    float* __restrict__ out) {
    int g = blockIdx.x;
    int j = threadIdx.x;
    __shared__ float hn[DLAT];
    hn[j] = h1[(size_t)g * DLAT + j] * fa[j] + fc[j];
    __syncthreads();
    float o = fb2[j];
    for (int k = 0; k < DLAT; k++) o += hn[k] * fW2[k * DLAT + j];
    out[(size_t)g * DLAT + j] = o;
}

// ================= launch =================
extern "C" void kernel_launch(void* const* d_in, const int* in_sizes, int n_in,
                              void* d_out, int out_size) {
    const float* x      = (const float*)d_in[0];
    const int*   ei     = (const int*)d_in[1];
    const int*   batch  = (const int*)d_in[2];
    const float* feats  = (const float*)d_in[3];
    const float* convW1 = (const float*)d_in[4];
    const float* convb1 = (const float*)d_in[5];
    const float* convg1 = (const float*)d_in[6];
    const float* convbb1= (const float*)d_in[7];
    const float* convW2 = (const float*)d_in[8];
    const float* convb2 = (const float*)d_in[9];
    const float* bng    = (const float*)d_in[10];
    const float* bnb    = (const float*)d_in[11];
    const float* fcW    = (const float*)d_in[12];
    const float* fcb    = (const float*)d_in[13];
    const float* cW1    = (const float*)d_in[14];
    const float* cb1    = (const float*)d_in[15];
    const float* cW2    = (const float*)d_in[16];
    const float* cb2    = (const float*)d_in[17];
    const float* fW1    = (const float*)d_in[18];
    const float* fb1    = (const float*)d_in[19];
    const float* fg     = (const float*)d_in[20];
    const float* fb_    = (const float*)d_in[21];
    const float* fW2    = (const float*)d_in[22];
    const float* fb2    = (const float*)d_in[23];
    float* dout = (float*)d_out;

    int nE = in_sizes[1] / 2;
    const int* src = ei;
    const int* dst = ei + nE;
    int M = in_sizes[0] / DH;
    int G = in_sizes[3] / NCOND;

    uint4 *p_a, *p_h, *p_Bpk1, *p_Bpk2;
    float *p_x, *p_bias, *p_sum, *p_sq, *p_pool, *p_pa, *p_pc, *p_h1, *p_fa, *p_fc;
    int *p_cnt, *p_rowptr, *p_bsum, *p_csr;
    cudaGetSymbolAddress((void**)&p_a, g_a);
    cudaGetSymbolAddress((void**)&p_h, g_h);
    cudaGetSymbolAddress((void**)&p_x, g_x);
    cudaGetSymbolAddress((void**)&p_Bpk1, g_Bpk1);
    cudaGetSymbolAddress((void**)&p_Bpk2, g_Bpk2);
    cudaGetSymbolAddress((void**)&p_bias, g_bias);
    cudaGetSymbolAddress((void**)&p_cnt, g_cnt);
    cudaGetSymbolAddress((void**)&p_rowptr, g_rowptr);
    cudaGetSymbolAddress((void**)&p_bsum, g_bsum);
    cudaGetSymbolAddress((void**)&p_csr, g_csr);
    cudaGetSymbolAddress((void**)&p_sum, g_sum);
    cudaGetSymbolAddress((void**)&p_sq, g_sumsq);
    cudaGetSymbolAddress((void**)&p_pool, g_pooled);
    cudaGetSymbolAddress((void**)&p_pa, g_pa);
    cudaGetSymbolAddress((void**)&p_pc, g_pc);
    cudaGetSymbolAddress((void**)&p_h1, g_h1);
    cudaGetSymbolAddress((void**)&p_fa, g_fa);
    cudaGetSymbolAddress((void**)&p_fc, g_fc);

    cudaFuncSetAttribute(gemm1_stats, cudaFuncAttributeMaxDynamicSharedMemorySize, GEMM_SMEM);
    cudaFuncSetAttribute(gemm2_pool, cudaFuncAttributeMaxDynamicSharedMemorySize, GEMM_SMEM);

    // ---- zero stats + pooled + cnt in one launch ----
    int cnt4n = N_NODES / 4;
    int zgrid = (cnt4n > N_GRAPHS * DH / 4 ? cnt4n : N_GRAPHS * DH / 4);
    zero3<<<(zgrid + 255) / 256, 256>>>(
        (float4*)p_sum, (float4*)p_sq, (float4*)p_pool, (float4*)p_cnt,
        N_GRAPHS * DH / 4, cnt4n);

    // ---- CSR build ----
    hist_k<<<(nE + 255) / 256, 256>>>(dst, p_cnt, nE);
    int nb = (M + 1023) / 1024;
    scan_block<<<nb, 1024>>>(p_cnt, p_rowptr, p_bsum, M);
    add_off2<<<nb, 256>>>(p_rowptr, p_bsum, p_cnt, M, nE, nb);
    scatter_k<<<(nE + 255) / 256, 256>>>(src, dst, p_cnt, p_csr, nE);

    // ---- pack all W1 in one launch ----
    wprep1all<<<3 * DH, DH>>>(convW1, p_Bpk1);

    int nTiles = (M + 255) / 256;
    for (int l = 0; l < 3; l++) {
        const float* xin = (l == 0) ? x : p_x;
        gather_f<<<(M + 7) / 8, 256>>>(
            (const float4*)xin, p_rowptr, p_csr, p_a, M);
        gemm1_stats<<<NSM, 256, GEMM_SMEM>>>(
            p_a, p_Bpk1 + (size_t)l * 4096, convb1 + l * DH, (uint32_t*)p_h,
            p_sum + l * DH, p_sq + l * DH, M, nTiles);
        wprep2f<<<DH, DH>>>(convW2 + (size_t)l * DH * DH, convb2 + l * DH,
                            p_sum + l * DH, p_sq + l * DH,
                            convg1 + l * DH, convbb1 + l * DH, (float)M, p_Bpk2, p_bias);
        gemm2_pool<<<NSM, 256, GEMM_SMEM>>>(
            p_h, p_Bpk2, p_bias, p_x, batch, p_pool, M, nTiles, (l == 2) ? 1 : 0);
    }

    colstats<<<DH, 256>>>(p_pool, G, DH, bng, bnb, p_pa, p_pc);
    head1<<<G, 64>>>(p_pool, p_pa, p_pc, fcW, fcb, feats, cW1, cb1, cW2, cb2, fW1, fb1, p_h1);
    colstats<<<DLAT, 256>>>(p_h1, G, DLAT, fg, fb_, p_fa, p_fc);
    head2<<<G, 64>>>(p_h1, p_fa, p_fc, fW2, fb2, dout);
}